// round 6
// baseline (speedup 1.0000x reference)
#include <cuda_runtime.h>

#define N_NODESC 50000
#define N_EDGESC 800000
#define E2C (N_EDGESC + N_NODESC)
#define D_INC 128
#define D_HIDC 64
#define D_OUTC 32

// ---------------- scratch (device globals; never referenced from host) --------
__device__ __align__(16) int   g_count[N_NODESC];
__device__ __align__(16) float g_attr_sum[N_NODESC];
__device__ __align__(16) float g_loop_attr[N_NODESC];
__device__ __align__(16) int   g_row_ptr[N_NODESC + 1];
__device__ __align__(16) int   g_cursor[N_NODESC];
__device__ __align__(16) int2  g_csr[E2C];                 // (src, attr-bits)
__device__ __align__(16) float g_xl [N_NODESC * D_HIDC];
__device__ __align__(16) float g_xr [N_NODESC * D_HIDC];
__device__ __align__(16) float g_h  [N_NODESC * D_HIDC];
__device__ __align__(16) float g_xl2[N_NODESC * D_OUTC];
__device__ __align__(16) float g_xr2[N_NODESC * D_OUTC];

__device__ __forceinline__ const float* lin_in_ptr(const float* xparam, int sel) {
    return (sel == 0) ? xparam : g_h;
}

// ---------------- preprocessing ------------------------------------------------
__global__ void init_kernel() {
    int i = blockIdx.x * blockDim.x + threadIdx.x;
    if (i < N_NODESC) {
        g_count[i] = 0;
        g_attr_sum[i] = 0.f;
        g_cursor[i] = 0;
    }
}

__global__ void count_kernel(const int* __restrict__ ei,
                             const float* __restrict__ ew) {
    int e = blockIdx.x * blockDim.x + threadIdx.x;
    if (e < N_EDGESC) {
        int d = ei[N_EDGESC + e];
        if ((unsigned)d < (unsigned)N_NODESC) {
            atomicAdd(&g_count[d], 1);
            atomicAdd(&g_attr_sum[d], ew[e]);
        }
    }
}

// single-block shuffle-based exclusive scan of (count[i]+1) -> row_ptr + loop_attr
__global__ void __launch_bounds__(1024) scan_kernel() {
    __shared__ int wsum[32];
    const int CH = (N_NODESC + 1023) / 1024;   // 49
    int t    = threadIdx.x;
    int lane = t & 31;
    int wid  = t >> 5;
    int beg = t * CH; if (beg > N_NODESC) beg = N_NODESC;
    int end = beg + CH; if (end > N_NODESC) end = N_NODESC;
    int s = 0;
    for (int i = beg; i < end; i++) {
        int c = g_count[i];
        s += c + 1;
        g_loop_attr[i] = g_attr_sum[i] / fmaxf((float)c, 1.0f);
    }
    // inclusive warp scan of per-thread totals
    int val = s;
#pragma unroll
    for (int o = 1; o < 32; o <<= 1) {
        int u = __shfl_up_sync(0xffffffffu, val, o);
        if (lane >= o) val += u;
    }
    if (lane == 31) wsum[wid] = val;
    __syncthreads();
    if (wid == 0) {
        int w = wsum[lane];
#pragma unroll
        for (int o = 1; o < 32; o <<= 1) {
            int u = __shfl_up_sync(0xffffffffu, w, o);
            if (lane >= o) w += u;
        }
        wsum[lane] = w;   // inclusive scan of warp sums
    }
    __syncthreads();
    int run = val - s + (wid ? wsum[wid - 1] : 0);   // exclusive prefix
    for (int i = beg; i < end; i++) {
        g_row_ptr[i] = run;
        run += g_count[i] + 1;
    }
    if (t == 0) g_row_ptr[N_NODESC] = E2C;
}

__global__ void scatter_kernel(const int* __restrict__ ei,
                               const float* __restrict__ ew) {
    int e = blockIdx.x * blockDim.x + threadIdx.x;
    if (e < N_EDGESC) {
        int d = ei[N_EDGESC + e];
        int s = ei[e];
        if ((unsigned)d < (unsigned)N_NODESC && (unsigned)s < (unsigned)N_NODESC) {
            int pos = g_row_ptr[d] + atomicAdd(&g_cursor[d], 1);
            g_csr[pos] = make_int2(s, __float_as_int(ew[e]));
        }
    } else if (e < E2C) {
        int v = e - N_EDGESC;
        int pos = g_row_ptr[v] + atomicAdd(&g_cursor[v], 1);
        g_csr[pos] = make_int2(v, __float_as_int(g_loop_attr[v]));
    }
}

// ---------------- fused linear: yl = x@Wl^T+bl, yr = x@Wr^T+br ------------------
// R_N=4 register tile: per k-iter 3x LDS.128 feeds 32 FFMA (FMA-bound).
template <int DI, int DO, int TN, int KC, int PAIR>
__global__ void __launch_bounds__(256) linear_fused_kernel(
    const float* __restrict__ xparam,
    const float* __restrict__ Wl, const float* __restrict__ bl,
    const float* __restrict__ Wr, const float* __restrict__ br,
    int insel) {
    constexpr int WS   = DO + 4;
    constexpr int XS   = TN + 4;
    constexpr int NT_H = DO / 4;
    constexpr int NT_N = 256 / NT_H;
    constexpr int R_N  = TN / NT_N;
    static_assert(DI % KC == 0 && R_N == 4, "tile config");
    __shared__ __align__(16) float Wls[KC * WS];
    __shared__ __align__(16) float Wrs[KC * WS];
    __shared__ __align__(16) float xs[KC * XS];
    const float* __restrict__ x = lin_in_ptr(xparam, insel);
    float* __restrict__ yl = PAIR ? g_xl2 : g_xl;
    float* __restrict__ yr = PAIR ? g_xr2 : g_xr;
    int t = threadIdx.x;
    int node0 = blockIdx.x * TN;
    int h0 = (t % NT_H) * 4;
    int n0 = (t / NT_H) * R_N;
    float accl[R_N][4], accr[R_N][4];
#pragma unroll
    for (int r = 0; r < R_N; r++)
#pragma unroll
        for (int c = 0; c < 4; c++) { accl[r][c] = 0.f; accr[r][c] = 0.f; }

    for (int c = 0; c < DI / KC; c++) {
        if (c) __syncthreads();
        for (int i = t; i < DO * KC; i += 256) {
            int r = i / KC, k = i % KC;
            Wls[k * WS + r] = Wl[r * DI + c * KC + k];
            Wrs[k * WS + r] = Wr[r * DI + c * KC + k];
        }
        for (int i = t; i < TN * KC; i += 256) {
            int n = i / KC, k = i % KC;
            int nd = node0 + n;
            xs[k * XS + n] = (nd < N_NODESC) ? x[nd * DI + c * KC + k] : 0.f;
        }
        __syncthreads();
#pragma unroll 4
        for (int k = 0; k < KC; k++) {
            float4 wl4 = *reinterpret_cast<const float4*>(&Wls[k * WS + h0]);
            float4 wr4 = *reinterpret_cast<const float4*>(&Wrs[k * WS + h0]);
            float4 xv4 = *reinterpret_cast<const float4*>(&xs[k * XS + n0]);
            float xvr[4] = {xv4.x, xv4.y, xv4.z, xv4.w};
#pragma unroll
            for (int r = 0; r < R_N; r++) {
                accl[r][0] = fmaf(xvr[r], wl4.x, accl[r][0]);
                accl[r][1] = fmaf(xvr[r], wl4.y, accl[r][1]);
                accl[r][2] = fmaf(xvr[r], wl4.z, accl[r][2]);
                accl[r][3] = fmaf(xvr[r], wl4.w, accl[r][3]);
                accr[r][0] = fmaf(xvr[r], wr4.x, accr[r][0]);
                accr[r][1] = fmaf(xvr[r], wr4.y, accr[r][1]);
                accr[r][2] = fmaf(xvr[r], wr4.z, accr[r][2]);
                accr[r][3] = fmaf(xvr[r], wr4.w, accr[r][3]);
            }
        }
    }
#pragma unroll
    for (int r = 0; r < R_N; r++) {
        int node = node0 + n0 + r;
        if (node < N_NODESC) {
            float4 o;
            o.x = accl[r][0] + bl[h0 + 0];
            o.y = accl[r][1] + bl[h0 + 1];
            o.z = accl[r][2] + bl[h0 + 2];
            o.w = accl[r][3] + bl[h0 + 3];
            *reinterpret_cast<float4*>(&yl[node * DO + h0]) = o;
            o.x = accr[r][0] + br[h0 + 0];
            o.y = accr[r][1] + br[h0 + 1];
            o.z = accr[r][2] + br[h0 + 2];
            o.w = accr[r][3] + br[h0 + 3];
            *reinterpret_cast<float4*>(&yr[node * DO + h0]) = o;
        }
    }
}

// ---------------- GATv2 node kernel: warp per node, lane-group per edge --------
// G lanes cooperate on one edge (PER=4 floats each, LDG.128); 32/G edges are
// processed per warp-iteration. Intra-group butterfly reduces the score; the
// cross-group combine of (ssum, acc) happens once per node at the end.
template <int DH, int G, int LAYER>
__global__ void __launch_bounds__(256) gat_node_kernel(
    const float* __restrict__ We, const float* __restrict__ att,
    const float* __restrict__ bias, float* __restrict__ outp) {
    constexpr int EPG = 32 / G;
    static_assert(DH == G * 4, "PER must be 4");
    const float* __restrict__ xl = LAYER ? g_xl2 : g_xl;
    const float* __restrict__ xr = LAYER ? g_xr2 : g_xr;
    float* __restrict__ out = LAYER ? outp : g_h;
    int v    = (blockIdx.x * blockDim.x + threadIdx.x) >> 5;
    int lane = threadIdx.x & 31;
    if (v >= N_NODESC) return;
    int grp = lane / G;        // which edge slot this lane serves
    int gl  = lane % G;        // lane within group
    int hb  = gl * 4;          // feature base for this lane

    float4 xrv  = *reinterpret_cast<const float4*>(xr + (size_t)v * DH + hb);
    float4 wev  = *reinterpret_cast<const float4*>(We + hb);
    float4 attv = *reinterpret_cast<const float4*>(att + hb);

    int beg = g_row_ptr[v], end = g_row_ptr[v + 1];     // end > beg (self loop)
    int niter = (end - beg + EPG - 1) / EPG;
    int idx = beg + grp;

    // 1-ahead pipeline per group
    int pidx = idx < end ? idx : end - 1;
    int2  ec = g_csr[pidx];
    float4 xc = *reinterpret_cast<const float4*>(xl + (size_t)ec.x * DH + hb);

    float ssum = 0.f;
    float4 acc = make_float4(0.f, 0.f, 0.f, 0.f);
    for (int it = 0; it < niter; it++) {
        int2  e  = ec;
        float4 xv = xc;
        int   my = idx;
        idx += EPG;
        int nidx = idx < end ? idx : end - 1;
        ec = g_csr[nidx];
        xc = *reinterpret_cast<const float4*>(xl + (size_t)ec.x * DH + hb);

        float a = __int_as_float(e.y);
        float m0 = fmaf(a, wev.x, xv.x + xrv.x); m0 = m0 > 0.f ? m0 : 0.2f * m0;
        float m1 = fmaf(a, wev.y, xv.y + xrv.y); m1 = m1 > 0.f ? m1 : 0.2f * m1;
        float m2 = fmaf(a, wev.z, xv.z + xrv.z); m2 = m2 > 0.f ? m2 : 0.2f * m2;
        float m3 = fmaf(a, wev.w, xv.w + xrv.w); m3 = m3 > 0.f ? m3 : 0.2f * m3;
        float sc = fmaf(attv.x, m0, fmaf(attv.y, m1, fmaf(attv.z, m2, attv.w * m3)));
#pragma unroll
        for (int o = G / 2; o > 0; o >>= 1) sc += __shfl_xor_sync(0xffffffffu, sc, o);
        float ex = (my < end) ? __expf(sc) : 0.f;
        ssum += ex;
        acc.x = fmaf(ex, xv.x, acc.x);
        acc.y = fmaf(ex, xv.y, acc.y);
        acc.z = fmaf(ex, xv.z, acc.z);
        acc.w = fmaf(ex, xv.w, acc.w);
    }
    // cross-group combine (once per node)
#pragma unroll
    for (int o = G; o < 32; o <<= 1) {
        ssum  += __shfl_xor_sync(0xffffffffu, ssum, o);
        acc.x += __shfl_xor_sync(0xffffffffu, acc.x, o);
        acc.y += __shfl_xor_sync(0xffffffffu, acc.y, o);
        acc.z += __shfl_xor_sync(0xffffffffu, acc.z, o);
        acc.w += __shfl_xor_sync(0xffffffffu, acc.w, o);
    }
    if (grp == 0) {
        float inv = 1.f / ssum;
        float4 bv = *reinterpret_cast<const float4*>(bias + hb);
        float o0 = fmaf(acc.x, inv, bv.x);
        float o1 = fmaf(acc.y, inv, bv.y);
        float o2 = fmaf(acc.z, inv, bv.z);
        float o3 = fmaf(acc.w, inv, bv.w);
        float4 res;
        if (LAYER == 0) {
            res.x = o0 > 0.f ? o0 : (__expf(o0) - 1.f);
            res.y = o1 > 0.f ? o1 : (__expf(o1) - 1.f);
            res.z = o2 > 0.f ? o2 : (__expf(o2) - 1.f);
            res.w = o3 > 0.f ? o3 : (__expf(o3) - 1.f);
        } else {
            res.x = (o0 > 20.f ? o0 : log1pf(__expf(o0))) + 1e-4f;
            res.y = (o1 > 20.f ? o1 : log1pf(__expf(o1))) + 1e-4f;
            res.z = (o2 > 20.f ? o2 : log1pf(__expf(o2))) + 1e-4f;
            res.w = (o3 > 20.f ? o3 : log1pf(__expf(o3))) + 1e-4f;
        }
        *reinterpret_cast<float4*>(out + (size_t)v * DH + hb) = res;
    }
}

// ---------------- launch --------------------------------------------------------
extern "C" void kernel_launch(void* const* d_in, const int* in_sizes, int n_in,
                              void* d_out, int out_size) {
    const float* x     = (const float*)d_in[0];
    const int*   ei    = (const int*)d_in[1];      // edge_index: int32
    const float* ew    = (const float*)d_in[2];
    const float* Wl1   = (const float*)d_in[3];
    const float* bl1   = (const float*)d_in[4];
    const float* Wr1   = (const float*)d_in[5];
    const float* br1   = (const float*)d_in[6];
    const float* We1   = (const float*)d_in[7];
    const float* att1  = (const float*)d_in[8];
    const float* bias1 = (const float*)d_in[9];
    const float* Wl2   = (const float*)d_in[10];
    const float* bl2   = (const float*)d_in[11];
    const float* Wr2   = (const float*)d_in[12];
    const float* br2   = (const float*)d_in[13];
    const float* We2   = (const float*)d_in[14];
    const float* att2  = (const float*)d_in[15];
    const float* bias2 = (const float*)d_in[16];
    float*       out   = (float*)d_out;

    // ---- graph preprocessing / CSR (shared by both layers) ----
    init_kernel<<<(N_NODESC + 255) / 256, 256>>>();
    count_kernel<<<(N_EDGESC + 255) / 256, 256>>>(ei, ew);
    scan_kernel<<<1, 1024>>>();
    scatter_kernel<<<(E2C + 255) / 256, 256>>>(ei, ew);

    const int GRID_GAT = (N_NODESC * 32 + 255) / 256;   // warp per node

    // ---- layer 1 ----
    linear_fused_kernel<D_INC, D_HIDC, 64, 32, 0><<<(N_NODESC + 63) / 64, 256>>>(
        x, Wl1, bl1, Wr1, br1, 0);
    gat_node_kernel<D_HIDC, 16, 0><<<GRID_GAT, 256>>>(We1, att1, bias1, out);

    // ---- layer 2 (input = g_h via insel=1) ----
    linear_fused_kernel<D_HIDC, D_OUTC, 128, 32, 1><<<(N_NODESC + 127) / 128, 256>>>(
        x, Wl2, bl2, Wr2, br2, 1);
    gat_node_kernel<D_OUTC, 8, 1><<<GRID_GAT, 256>>>(We2, att2, bias2, out);
}